// round 14
// baseline (speedup 1.0000x reference)
#include <cuda_runtime.h>
#include <cstdint>

#define BH   64
#define S    2048
#define RNK  64
#define D    64
#define NELEM (BH*S*RNK)
#define NSPLIT 8

#define JAX_PARTITIONABLE 1

__device__ __align__(16) float g_Rp  [NELEM];
__device__ __align__(16) float g_ls  [NELEM];
__device__ __align__(16) float g_part[5*BH*NSPLIT*4096];
__device__ float g_invL[BH*S];
__device__ float g_invR[BH*RNK];
__device__ float g_rowdot[BH*RNK];
__device__ float g_pnorm[BH*RNK*16];
__device__ float g_G [BH*RNK*RNK];
__device__ float g_H [BH*RNK*RNK];
__device__ float g_P [BH*RNK*D];
__device__ float g_RK[BH*RNK*D];
__device__ float g_W [BH*RNK*D];

__host__ __device__ inline uint32_t rotl_(uint32_t x, int r) {
#ifdef __CUDA_ARCH__
    return __funnelshift_l(x, x, r);
#else
    return (x << r) | (x >> (32 - r));
#endif
}

__host__ __device__ inline void tf2x32(uint32_t k0, uint32_t k1,
                                       uint32_t x0, uint32_t x1,
                                       uint32_t* o0, uint32_t* o1) {
    uint32_t ks0 = k0, ks1 = k1, ks2 = k0 ^ k1 ^ 0x1BD11BDAu;
    x0 += ks0; x1 += ks1;
#define TF_RND(r) { x0 += x1; x1 = rotl_(x1, r); x1 ^= x0; }
    TF_RND(13) TF_RND(15) TF_RND(26) TF_RND(6)
    x0 += ks1; x1 += ks2 + 1u;
    TF_RND(17) TF_RND(29) TF_RND(16) TF_RND(24)
    x0 += ks2; x1 += ks0 + 2u;
    TF_RND(13) TF_RND(15) TF_RND(26) TF_RND(6)
    x0 += ks0; x1 += ks1 + 3u;
    TF_RND(17) TF_RND(29) TF_RND(16) TF_RND(24)
    x0 += ks1; x1 += ks2 + 4u;
    TF_RND(13) TF_RND(15) TF_RND(26) TF_RND(6)
    x0 += ks2; x1 += ks0 + 5u;
#undef TF_RND
    *o0 = x0; *o1 = x1;
}

__device__ inline float bits_to_unit(uint32_t bits) {
    return __uint_as_float((bits >> 9) | 0x3F800000u) - 1.0f;
}

__device__ inline uint32_t rbits(uint32_t ka, uint32_t kb, uint32_t idx) {
    uint32_t o0, o1;
#if JAX_PARTITIONABLE
    tf2x32(ka, kb, 0u, idx, &o0, &o1);
    return o0 ^ o1;
#else
    const uint32_t HN = NELEM / 2;
    if (idx < HN) { tf2x32(ka, kb, idx, idx + HN, &o0, &o1); return o0; }
    tf2x32(ka, kb, idx - HN, idx, &o0, &o1); return o1;
#endif
}

__global__ void k_initL(uint32_t la, uint32_t lb) {
    int row = blockIdx.x * 8 + (threadIdx.x >> 5);
    int lane = threadIdx.x & 31;
    int base = row * RNK;
    float u0 = bits_to_unit(rbits(la, lb, (uint32_t)(base + lane)));
    float u1 = bits_to_unit(rbits(la, lb, (uint32_t)(base + 32 + lane)));
    float v0 = 0.125f + (0.002f * u0 - 0.001f);
    float v1 = 0.125f + (0.002f * u1 - 0.001f);
    float ss = v0 * v0 + v1 * v1;
    #pragma unroll
    for (int o = 16; o > 0; o >>= 1) ss += __shfl_xor_sync(0xffffffffu, ss, o);
    float n = sqrtf(ss);
    float inv = (n > 0.f) ? (1.0f / n) : 0.0f;
    g_ls[base + lane]      = (n > 0.f) ? v0 / n : v0;
    g_ls[base + 32 + lane] = (n > 0.f) ? v1 / n : v1;
    if (lane == 0) g_invL[row] = inv;
}

__global__ void k_initR(uint32_t ra, uint32_t rb) {
    int g4 = blockIdx.x * blockDim.x + threadIdx.x;
    int e = g4 * 4;
    float4 o;
    o.x = 0.022097086912079608f + (0.002f * bits_to_unit(rbits(ra, rb, e))     - 0.001f);
    o.y = 0.022097086912079608f + (0.002f * bits_to_unit(rbits(ra, rb, e + 1)) - 0.001f);
    o.z = 0.022097086912079608f + (0.002f * bits_to_unit(rbits(ra, rb, e + 2)) - 0.001f);
    o.w = 0.022097086912079608f + (0.002f * bits_to_unit(rbits(ra, rb, e + 3)) - 0.001f);
    ((float4*)g_Rp)[g4] = o;
}

// one-time initial R row norms (no rs materialization). grid(BH*RNK) x 256
__global__ void k_prepN() {
    int row = blockIdx.x;
    const float* p = g_Rp + (size_t)row * S;
    int tid = threadIdx.x;
    float4 a = ((const float4*)p)[tid];
    float4 b = ((const float4*)p)[tid + 256];
    float ss = a.x*a.x + a.y*a.y + a.z*a.z + a.w*a.w
             + b.x*b.x + b.y*b.y + b.z*b.z + b.w*b.w;
    #pragma unroll
    for (int o = 16; o > 0; o >>= 1) ss += __shfl_xor_sync(0xffffffffu, ss, o);
    __shared__ float red[8];
    if ((tid & 31) == 0) red[tid >> 5] = ss;
    __syncthreads();
    if (tid == 0) {
        float n = sqrtf(red[0]+red[1]+red[2]+red[3]+red[4]+red[5]+red[6]+red[7]);
        g_invR[row] = (n > 0.f) ? (1.0f / n) : 0.0f;
    }
}

// reduce per-tile partial norms -> invR. grid(16) x 256
__global__ void k_normR() {
    int row = blockIdx.x * blockDim.x + threadIdx.x;
    const float* p = g_pnorm + row * 16;
    float s = p[0];
    #pragma unroll
    for (int t = 1; t < 16; t++) s += p[t];
    float n = sqrtf(s);
    g_invR[row] = (n > 0.f) ? (1.0f / n) : 0.0f;
}

// Fused-pair split-K gemm; pair>=1 reads Rp and applies invR on the fly.
__global__ void k_gemmF(const float* __restrict__ q, const float* __restrict__ kin,
                        const float* __restrict__ vin, int ybase) {
    __shared__ __align__(16) float buf[32 * 132];
    __shared__ float sIv[64];
    int bh = blockIdx.x, pair = ybase + blockIdx.y, kz = blockIdx.z;
    int tid = threadIdx.x;
    int ty = tid >> 4, tx = tid & 15;
    int kbeg = kz * (S / NSPLIT);
    float acc[8][8];
    #pragma unroll
    for (int a = 0; a < 8; a++)
        #pragma unroll
        for (int b = 0; b < 8; b++) acc[a][b] = 0.f;

    const float* rhs = (pair == 0) ? (q + bh * S * D)
                     : (pair == 1) ? (kin + bh * S * D)
                                   : (vin + bh * S * D);
    float rscale = (pair == 0) ? 0.125f : 1.0f;
    if (pair >= 1 && tid < 64) sIv[tid] = g_invR[bh * 64 + tid];
    __syncthreads();

    for (int t0 = kbeg; t0 < kbeg + S / NSPLIT; t0 += 32) {
        if (pair == 0) {
            const float* lsb = g_ls + bh * S * RNK;
            #pragma unroll
            for (int p = 0; p < 8; p++) {
                int idx = p * 128 + tid;
                int row = idx >> 5, c4 = idx & 31;
                if (c4 < 16) {
                    float4 x = *reinterpret_cast<const float4*>(&lsb[(t0 + row) * RNK + c4 * 4]);
                    x.x *= x.x; x.y *= x.y; x.z *= x.z; x.w *= x.w;
                    *reinterpret_cast<float4*>(&buf[row * 132 + c4 * 4]) = x;
                } else {
                    float4 x = *reinterpret_cast<const float4*>(&rhs[(t0 + row) * D + (c4 - 16) * 4]);
                    x.x *= rscale; x.y *= rscale; x.z *= rscale; x.w *= rscale;
                    *reinterpret_cast<float4*>(&buf[row * 132 + 64 + (c4 - 16) * 4]) = x;
                }
            }
        } else {
            const float* rpb = g_Rp + (size_t)bh * RNK * S;
            #pragma unroll
            for (int p = 0; p < 16; p++) {
                int idx = p * 128 + tid;
                int j = idx >> 5, tt = idx & 31;
                float x = rpb[j * S + t0 + tt] * sIv[j];
                buf[tt * 132 + j] = x * x;
            }
            #pragma unroll
            for (int p = 0; p < 4; p++) {
                int idx = p * 128 + tid;
                int row = idx >> 4, c4 = idx & 15;
                float4 x = *reinterpret_cast<const float4*>(&rhs[(t0 + row) * D + c4 * 4]);
                *reinterpret_cast<float4*>(&buf[row * 132 + 64 + c4 * 4]) = x;
            }
        }
        __syncthreads();
        #pragma unroll 4
        for (int kk = 0; kk < 32; kk++) {
            float4 a0 = *reinterpret_cast<const float4*>(&buf[kk * 132 + ty * 8]);
            float4 a1 = *reinterpret_cast<const float4*>(&buf[kk * 132 + ty * 8 + 4]);
            float4 b0 = *reinterpret_cast<const float4*>(&buf[kk * 132 + tx * 8]);
            float4 b1 = *reinterpret_cast<const float4*>(&buf[kk * 132 + tx * 8 + 4]);
            float av[8] = {a0.x,a0.y,a0.z,a0.w,a1.x,a1.y,a1.z,a1.w};
            float bv[8] = {b0.x,b0.y,b0.z,b0.w,b1.x,b1.y,b1.z,b1.w};
            #pragma unroll
            for (int a = 0; a < 8; a++)
                #pragma unroll
                for (int b = 0; b < 8; b++) acc[a][b] += av[a] * bv[b];
        }
        __syncthreads();
    }

    int right = (tx >= 8);
    int mode = (pair == 0) ? (right ? 1 : 0)
             : (pair == 1) ? (right ? 3 : 2)
                           : 4;
    if (pair == 2 && !right) return;
    int cloc = (tx & 7) * 8;
    float* out = g_part + (((size_t)mode * BH + bh) * NSPLIT + kz) * 4096;
    #pragma unroll
    for (int a = 0; a < 8; a++) {
        int j = ty * 8 + a;
        *reinterpret_cast<float4*>(&out[j * 64 + cloc])     = make_float4(acc[a][0], acc[a][1], acc[a][2], acc[a][3]);
        *reinterpret_cast<float4*>(&out[j * 64 + cloc + 4]) = make_float4(acc[a][4], acc[a][5], acc[a][6], acc[a][7]);
    }
}

__global__ void k_gred(int modebase) {
    int gid = blockIdx.x * blockDim.x + threadIdx.x;
    int e = gid & 4095;
    int bh = (gid >> 12) & 63;
    int mode = modebase + (gid >> 18);
    const float* p = g_part + ((size_t)(mode * BH + bh) * NSPLIT) * 4096 + e;
    float s = p[0];
    #pragma unroll
    for (int t = 1; t < NSPLIT; t++) s += p[t * 4096];
    float* dst;
    switch (mode) { case 0: dst = g_H; break; case 1: dst = g_P; break;
                    case 2: dst = g_G; break; case 3: dst = g_RK; break;
                    default: dst = g_W; break; }
    dst[bh * 4096 + e] = s;
}

__global__ void k_rowdotA() {
    int row = blockIdx.x * 8 + (threadIdx.x >> 5);
    int lane = threadIdx.x & 31;
    int bh = row >> 6, j = row & 63;
    const float* Hr = g_H  + bh * 4096 + j * 64;
    const float* Gr = g_G  + bh * 4096 + j * 64;
    const float* Pr = g_P  + bh * 4096 + j * 64;
    const float* Kr = g_RK + bh * 4096 + j * 64;
    float s = Hr[lane] * Gr[lane] + Hr[lane + 32] * Gr[lane + 32]
            - Pr[lane] * Kr[lane] - Pr[lane + 32] * Kr[lane + 32];
    #pragma unroll
    for (int o = 16; o > 0; o >>= 1) s += __shfl_xor_sync(0xffffffffu, s, o);
    if (lane == 0) g_rowdot[row] = 2.0f * s;
}

// merged update kernel. grid(BH, 32) x 128. y<16 -> L tile i0=y*128; y>=16 -> R tile t0=(y-16)*128.
__global__ void k_updateLR(const float* __restrict__ q, const float* __restrict__ kin) {
    __shared__ __align__(16) float AT[32 * 132];
    __shared__ __align__(16) float Bs[32 * 68];
    __shared__ float sInv[64], sRd[64];
    __shared__ float red[16 * 64];
    int bh = blockIdx.x;
    int tid = threadIdx.x;
    int ty = tid >> 3, tx = tid & 7;

    float acc[8][8];
    #pragma unroll
    for (int a = 0; a < 8; a++)
        #pragma unroll
        for (int b = 0; b < 8; b++) acc[a][b] = 0.f;

    if (blockIdx.y < 16) {
        // ------- L update -------
        int i0 = blockIdx.y * 128;
        const float* lsb = g_ls + (size_t)bh * S * RNK + (size_t)i0 * RNK;
        const float* qb  = q + (size_t)bh * S * D + (size_t)i0 * D;
        const float* Gb  = g_G  + bh * 4096;
        const float* RKb = g_RK + bh * 4096;

        #pragma unroll
        for (int c = 0; c < 4; c++) {
            int kb = (c & 1) * 32;
            #pragma unroll
            for (int p = 0; p < 32; p++) {
                int e = p * 128 + tid;
                int i = e >> 5, kk = e & 31;
                float x;
                if (c < 2) { x = lsb[i * RNK + kb + kk]; x = x * x; }
                else       { x = 0.125f * qb[i * D + kb + kk]; }
                AT[kk * 132 + i] = x;
            }
            #pragma unroll
            for (int p = 0; p < 16; p++) {
                int e = p * 128 + tid;
                if (c < 2) { int r0 = e >> 6, cc = e & 63; Bs[r0 * 68 + cc] = Gb[(kb + r0) * 64 + cc]; }
                else       { Bs[(e & 31) * 68 + (e >> 5)] = -RKb[(e >> 5) * 64 + kb + (e & 31)]; }
            }
            __syncthreads();
            #pragma unroll 4
            for (int kk = 0; kk < 32; kk++) {
                float4 a0 = *reinterpret_cast<const float4*>(&AT[kk * 132 + ty * 8]);
                float4 a1 = *reinterpret_cast<const float4*>(&AT[kk * 132 + ty * 8 + 4]);
                float4 b0 = *reinterpret_cast<const float4*>(&Bs[kk * 68 + tx * 8]);
                float4 b1 = *reinterpret_cast<const float4*>(&Bs[kk * 68 + tx * 8 + 4]);
                float av[8] = {a0.x,a0.y,a0.z,a0.w,a1.x,a1.y,a1.z,a1.w};
                float bv[8] = {b0.x,b0.y,b0.z,b0.w,b1.x,b1.y,b1.z,b1.w};
                #pragma unroll
                for (int a = 0; a < 8; a++)
                    #pragma unroll
                    for (int b = 0; b < 8; b++) acc[a][b] += av[a] * bv[b];
            }
            __syncthreads();
        }

        #pragma unroll
        for (int a = 0; a < 8; a++) {
            int i = i0 + ty * 8 + a;
            float* lsrow = g_ls + ((size_t)bh * S + i) * RNK + tx * 8;
            float4 l0 = *reinterpret_cast<const float4*>(lsrow);
            float4 l1 = *reinterpret_cast<const float4*>(lsrow + 4);
            float ls[8] = {l0.x,l0.y,l0.z,l0.w,l1.x,l1.y,l1.z,l1.w};
            float dl[8];
            float cpart = 0.f;
            #pragma unroll
            for (int b = 0; b < 8; b++) {
                dl[b] = acc[a][b] * 2.0f * ls[b];
                cpart += ls[b] * dl[b];
            }
            #pragma unroll
            for (int o = 1; o < 8; o <<= 1) cpart += __shfl_xor_sync(0xffffffffu, cpart, o);
            float inv = g_invL[bh * S + i];
            float norm_old = (inv > 0.f) ? (1.0f / inv) : 0.0f;
            float nv[8]; float ss = 0.f;
            #pragma unroll
            for (int b = 0; b < 8; b++) {
                float p0 = (inv > 0.f) ? ls[b] * norm_old : ls[b];
                nv[b] = p0 - inv * (dl[b] - ls[b] * cpart);
                ss += nv[b] * nv[b];
            }
            #pragma unroll
            for (int o = 1; o < 8; o <<= 1) ss += __shfl_xor_sync(0xffffffffu, ss, o);
            float nn = sqrtf(ss);
            float rinv = (nn > 0.f) ? (1.0f / nn) : 0.0f;
            #pragma unroll
            for (int b = 0; b < 8; b++) nv[b] = (nn > 0.f) ? nv[b] * rinv : nv[b];
            *reinterpret_cast<float4*>(lsrow)     = make_float4(nv[0], nv[1], nv[2], nv[3]);
            *reinterpret_cast<float4*>(lsrow + 4) = make_float4(nv[4], nv[5], nv[6], nv[7]);
            if (tx == 0) g_invL[bh * S + i] = rinv;
        }
    } else {
        // ------- R update -------
        int tile = blockIdx.y - 16;
        int t0 = tile * 128;
        const float* rpb = g_Rp + (size_t)bh * RNK * S;
        const float* kb_ = kin + (size_t)bh * S * D + (size_t)t0 * D;
        const float* Hb  = g_H + bh * 4096;
        const float* Pb  = g_P + bh * 4096;

        if (tid < 64) {
            sInv[tid] = g_invR[bh * 64 + tid];
            sRd [tid] = g_rowdot[bh * 64 + tid];
        }
        __syncthreads();

        #pragma unroll
        for (int c = 0; c < 4; c++) {
            int kb = (c & 1) * 32;
            if (c < 2) {
                #pragma unroll
                for (int p = 0; p < 32; p++) {
                    float iv = sInv[kb + p];
                    float x = rpb[(kb + p) * S + t0 + tid] * iv;
                    AT[p * 132 + tid] = x * x;
                }
                #pragma unroll
                for (int p = 0; p < 16; p++) {
                    int e = p * 128 + tid;
                    int r0 = e >> 6, cc = e & 63;
                    Bs[r0 * 68 + cc] = Hb[(kb + r0) * 64 + cc];
                }
            } else {
                #pragma unroll
                for (int p = 0; p < 32; p++) {
                    int e = p * 128 + tid;
                    int t = e >> 5, d = e & 31;
                    AT[d * 132 + t] = kb_[t * D + kb + d];
                }
                #pragma unroll
                for (int p = 0; p < 16; p++) {
                    int e = p * 128 + tid;
                    int j = e >> 5, d = e & 31;
                    Bs[d * 68 + j] = -Pb[j * 64 + kb + d];
                }
            }
            __syncthreads();
            #pragma unroll 4
            for (int kk = 0; kk < 32; kk++) {
                float4 a0 = *reinterpret_cast<const float4*>(&AT[kk * 132 + ty * 8]);
                float4 a1 = *reinterpret_cast<const float4*>(&AT[kk * 132 + ty * 8 + 4]);
                float4 b0 = *reinterpret_cast<const float4*>(&Bs[kk * 68 + tx * 8]);
                float4 b1 = *reinterpret_cast<const float4*>(&Bs[kk * 68 + tx * 8 + 4]);
                float av[8] = {a0.x,a0.y,a0.z,a0.w,a1.x,a1.y,a1.z,a1.w};
                float bv[8] = {b0.x,b0.y,b0.z,b0.w,b1.x,b1.y,b1.z,b1.w};
                #pragma unroll
                for (int a = 0; a < 8; a++)
                    #pragma unroll
                    for (int b = 0; b < 8; b++) acc[a][b] += av[a] * bv[b];
            }
            __syncthreads();
        }

        // epilogue: thread owns t = t0+ty*8+a, j = tx*8+b; writes Rp + partial norms
        #pragma unroll
        for (int b = 0; b < 8; b++) {
            int j = tx * 8 + b;
            float inv = sInv[j], rd = sRd[j];
            const float* rsrc = rpb + (size_t)j * S + t0 + ty * 8;
            float* rdst = g_Rp + (size_t)bh * RNK * S + (size_t)j * S + t0 + ty * 8;
            float4 r0 = *reinterpret_cast<const float4*>(rsrc);
            float4 r1 = *reinterpret_cast<const float4*>(rsrc + 4);
            float rp[8] = {r0.x,r0.y,r0.z,r0.w,r1.x,r1.y,r1.z,r1.w};
            float nv[8]; float pn = 0.f;
            #pragma unroll
            for (int a = 0; a < 8; a++) {
                float rs = rp[a] * inv;
                float dt = acc[a][b] * 2.0f * rs;
                float pp = (inv > 0.f) ? rp[a] : rp[a];   // pp == Rp either way
                nv[a] = pp - inv * (dt - rs * rd);
                pn += nv[a] * nv[a];
            }
            *reinterpret_cast<float4*>(rdst)     = make_float4(nv[0], nv[1], nv[2], nv[3]);
            *reinterpret_cast<float4*>(rdst + 4) = make_float4(nv[4], nv[5], nv[6], nv[7]);
            red[ty * 64 + j] = pn;
        }
        __syncthreads();
        if (tid < 64) {
            float s = red[tid];
            #pragma unroll
            for (int t = 1; t < 16; t++) s += red[t * 64 + tid];
            g_pnorm[(bh * 64 + tid) * 16 + tile] = s;
        }
    }
}

// out = lsq^2 @ W. grid(64,16) x 256
__global__ void k_out(float* __restrict__ out) {
    __shared__ float Ws[64 * 65];
    int bh = blockIdx.x;
    for (int e = threadIdx.x; e < 4096; e += 256)
        Ws[(e >> 6) * 65 + (e & 63)] = g_W[bh * 4096 + e];
    __syncthreads();
    int w = threadIdx.x >> 5, lane = threadIdx.x & 31;
    for (int g = 0; g < 4; g++) {
        int i0 = blockIdx.y * 128 + w * 16 + g * 4;
        float lq0[4], lq1[4], o0[4], o1[4];
        #pragma unroll
        for (int r = 0; r < 4; r++) {
            int base = bh * S * RNK + (i0 + r) * RNK;
            float a = g_ls[base + lane], b = g_ls[base + 32 + lane];
            lq0[r] = a * a; lq1[r] = b * b;
            o0[r] = 0.f; o1[r] = 0.f;
        }
        #pragma unroll 4
        for (int j = 0; j < 64; j++) {
            float x0 = Ws[j * 65 + lane], x1 = Ws[j * 65 + 32 + lane];
            #pragma unroll
            for (int r = 0; r < 4; r++) {
                float lv = (j < 32) ? __shfl_sync(0xffffffffu, lq0[r], j)
                                    : __shfl_sync(0xffffffffu, lq1[r], j - 32);
                o0[r] += lv * x0; o1[r] += lv * x1;
            }
        }
        #pragma unroll
        for (int r = 0; r < 4; r++) {
            int ob = bh * S * D + (i0 + r) * D;
            out[ob + lane]      = o0[r];
            out[ob + 32 + lane] = o1[r];
        }
    }
}

extern "C" void kernel_launch(void* const* d_in, const int* in_sizes, int n_in,
                              void* d_out, int out_size) {
    const float* q = (const float*)d_in[0];
    const float* k = (const float*)d_in[1];
    const float* v = (const float*)d_in[2];
    float* out = (float*)d_out;

    uint32_t k1a, k1b, k2a, k2b;
#if JAX_PARTITIONABLE
    tf2x32(0u, 42u, 0u, 0u, &k1a, &k1b);
    tf2x32(0u, 42u, 0u, 1u, &k2a, &k2b);
#else
    { uint32_t a0, b0, a1, b1;
      tf2x32(0u, 42u, 0u, 2u, &a0, &b0);
      tf2x32(0u, 42u, 1u, 3u, &a1, &b1);
      k1a = a0; k1b = a1; k2a = b0; k2b = b1; }
#endif

    k_initL<<<BH * S / 8, 256>>>(k1a, k1b);
    k_initR<<<NELEM / 4 / 256, 256>>>(k2a, k2b);
    k_prepN<<<BH * RNK, 256>>>();
    for (int step = 0; step < 8; step++) {
        k_gemmF<<<dim3(BH, 2, NSPLIT), 128>>>(q, k, v, 0);    // H|P and G|RK partials
        k_gred<<<4 * BH * 4096 / 256, 256>>>(0);
        k_rowdotA<<<BH * RNK / 8, 256>>>();
        k_updateLR<<<dim3(BH, 32), 128>>>(q, k);
        k_normR<<<16, 256>>>();
    }
    k_gemmF<<<dim3(BH, 1, NSPLIT), 128>>>(q, k, v, 2);        // W partials
    k_gred<<<BH * 4096 / 256, 256>>>(4);
    k_out<<<dim3(BH, 16), 256>>>(out);
}